// round 3
// baseline (speedup 1.0000x reference)
#include <cuda_runtime.h>
#include <cuda_bf16.h>
#include <cstdint>

// ---------------- scratch (static __device__, no allocation) ----------------
#define MAXB 32
#define MAXN 500000
#define CAP  4096

__device__ float        g_pooled[MAXB * 512];
__device__ float        g_query [MAXB * 512];
__device__ float        g_scores[(size_t)MAXB * MAXN];   // 64 MB
__device__ unsigned int g_hist  [MAXB * 4096];
__device__ unsigned int g_thresh[MAXB];
__device__ int          g_ccount[MAXB];
__device__ unsigned int g_cu    [MAXB * CAP];
__device__ int          g_cidx  [MAXB * CAP];

__device__ __forceinline__ unsigned int fmono(float f) {
    unsigned int u = __float_as_uint(f);
    return (u & 0x80000000u) ? ~u : (u | 0x80000000u);
}
__device__ __forceinline__ float funmono(unsigned int u) {
    unsigned int o = (u & 0x80000000u) ? (u ^ 0x80000000u) : ~u;
    return __uint_as_float(o);
}

// packed fp32x2 FMA (FFMA2) — only reachable via PTX on sm_103a
__device__ __forceinline__ float2 ffma2(float2 a, float2 b, float2 c) {
    unsigned long long au = *reinterpret_cast<unsigned long long*>(&a);
    unsigned long long bu = *reinterpret_cast<unsigned long long*>(&b);
    unsigned long long cu = *reinterpret_cast<unsigned long long*>(&c);
    unsigned long long du;
    asm("fma.rn.f32x2 %0, %1, %2, %3;" : "=l"(du) : "l"(au), "l"(bu), "l"(cu));
    return *reinterpret_cast<float2*>(&du);
}

#define INV_SQRT_D 0.04419417382415922f   // 1/sqrt(512)

// ---------------- K0: zero hist + counters ----------------
__global__ void k_zero() {
    int total = MAXB * 4096 + MAXB;
    for (int i = blockIdx.x * blockDim.x + threadIdx.x; i < total;
         i += gridDim.x * blockDim.x) {
        if (i < MAXB * 4096) g_hist[i] = 0u;
        else                 g_ccount[i - MAXB * 4096] = 0;
    }
}

// ---------------- K1: pooled = mean(hidden, axis=T) ----------------
__global__ void k_mean(const float* __restrict__ hidden, int T) {
    int b  = blockIdx.x;
    int d  = blockIdx.y * 128 + threadIdx.x;
    const float* hp = hidden + (size_t)b * T * 512 + d;
    float s0 = 0.f, s1 = 0.f, s2 = 0.f, s3 = 0.f, s4 = 0.f, s5 = 0.f, s6 = 0.f, s7 = 0.f;
    int t = 0;
    for (; t + 8 <= T; t += 8) {
        s0 += hp[(size_t)(t + 0) * 512]; s1 += hp[(size_t)(t + 1) * 512];
        s2 += hp[(size_t)(t + 2) * 512]; s3 += hp[(size_t)(t + 3) * 512];
        s4 += hp[(size_t)(t + 4) * 512]; s5 += hp[(size_t)(t + 5) * 512];
        s6 += hp[(size_t)(t + 6) * 512]; s7 += hp[(size_t)(t + 7) * 512];
    }
    float s = ((s0 + s1) + (s2 + s3)) + ((s4 + s5) + (s6 + s7));
    for (; t < T; t++) s += hp[(size_t)t * 512];
    g_pooled[b * 512 + d] = s / (float)T;
}

// ---------------- K2: query = pooled @ W + b ----------------
__global__ void k_query(const float* __restrict__ W, const float* __restrict__ bias) {
    __shared__ float p[512];
    int b = blockIdx.x, tid = threadIdx.x;          // 128 threads
    for (int i = tid; i < 512; i += 128) p[i] = g_pooled[b * 512 + i];
    __syncthreads();
    int d = tid * 4;
    float a0 = 0.f, a1 = 0.f, a2 = 0.f, a3 = 0.f;
#pragma unroll 4
    for (int k = 0; k < 512; k++) {
        float4 wv = *reinterpret_cast<const float4*>(W + (size_t)k * 512 + d);
        float pv = p[k];
        a0 += pv * wv.x; a1 += pv * wv.y; a2 += pv * wv.z; a3 += pv * wv.w;
    }
    float4 bv = *reinterpret_cast<const float4*>(bias + d);
    float4 r  = make_float4(a0 + bv.x, a1 + bv.y, a2 + bv.z, a3 + bv.w);
    *reinterpret_cast<float4*>(g_query + (size_t)b * 512 + d) = r;
}

// ---------------- K3: scores[m][n] = dot(query[m], keys[n]) / sqrt(D) ----------------
// Tile: 128 keys x 32 queries, K-chunk 64. 256 threads; each thread: 4 keys x 4 queries,
// accumulating K-pairs via FFMA2.
#define TN 128
#define KC 64
__global__ __launch_bounds__(256) void k_scores(const float* __restrict__ keys, int N) {
    __shared__ float2 ks[KC / 2][TN + 1];   // pad -> 2-way max conflicts on store
    __shared__ float2 qs[KC / 2][32];
    int n0  = blockIdx.x * TN;
    int tid = threadIdx.x;
    int kg  = tid & 31;     // key group (lane)
    int qg  = tid >> 5;     // query group (warp id, 0..7)

    float2 acc[4][4];
#pragma unroll
    for (int i = 0; i < 4; i++)
#pragma unroll
        for (int j = 0; j < 4; j++) acc[i][j] = make_float2(0.f, 0.f);

    for (int c = 0; c < 512; c += KC) {
        // keys chunk: 128 rows x 64 cols = 2048 float4s / 256 threads = 8 iters
#pragma unroll
        for (int it = 0; it < 8; it++) {
            int v   = it * 256 + tid;
            int row = v >> 4;
            int c4  = v & 15;
            float4 val = make_float4(0.f, 0.f, 0.f, 0.f);
            int n = n0 + row;
            if (n < N)
                val = *reinterpret_cast<const float4*>(keys + (size_t)n * 512 + c + c4 * 4);
            ks[c4 * 2    ][row] = make_float2(val.x, val.y);
            ks[c4 * 2 + 1][row] = make_float2(val.z, val.w);
        }
        // queries chunk: 32 rows x 64 cols = 512 float4s / 256 threads = 2 iters
#pragma unroll
        for (int it = 0; it < 2; it++) {
            int v  = it * 256 + tid;
            if (v < 512) {
                int m  = v >> 4;
                int c4 = v & 15;
                float4 val = *reinterpret_cast<const float4*>(g_query + (size_t)m * 512 + c + c4 * 4);
                qs[c4 * 2    ][m] = make_float2(val.x, val.y);
                qs[c4 * 2 + 1][m] = make_float2(val.z, val.w);
            }
        }
        __syncthreads();
#pragma unroll
        for (int kp = 0; kp < KC / 2; kp++) {
            float2 kv[4], qv[4];
#pragma unroll
            for (int i = 0; i < 4; i++) kv[i] = ks[kp][kg + 32 * i];
#pragma unroll
            for (int j = 0; j < 4; j++) qv[j] = qs[kp][qg + 8 * j];
#pragma unroll
            for (int i = 0; i < 4; i++)
#pragma unroll
                for (int j = 0; j < 4; j++) acc[i][j] = ffma2(kv[i], qv[j], acc[i][j]);
        }
        __syncthreads();
    }
#pragma unroll
    for (int j = 0; j < 4; j++) {
        int m = qg + 8 * j;
#pragma unroll
        for (int i = 0; i < 4; i++) {
            int n = n0 + kg + 32 * i;
            if (n < N)
                g_scores[(size_t)m * N + n] = (acc[i][j].x + acc[i][j].y) * INV_SQRT_D;
        }
    }
}

// ---------------- K4: 12-bit histogram of monotone keys, per row ----------------
__global__ void k_hist(int N) {
    __shared__ unsigned int h[4096];
    int row  = blockIdx.y;
    int base = blockIdx.x * 8192;
    for (int i = threadIdx.x; i < 4096; i += 256) h[i] = 0u;
    __syncthreads();
    const float* sr = g_scores + (size_t)row * N;
    for (int i = threadIdx.x; i < 8192; i += 256) {
        int idx = base + i;
        if (idx < N) atomicAdd(&h[fmono(sr[idx]) >> 20], 1u);
    }
    __syncthreads();
    for (int i = threadIdx.x; i < 4096; i += 256)
        if (h[i]) atomicAdd(&g_hist[row * 4096 + i], h[i]);
}

// ---------------- K5: find threshold bin so that count(bins >= b*) >= max_k ----------------
__global__ void k_thresh(const int* __restrict__ pmk) {
    __shared__ unsigned int bins[4096];
    __shared__ unsigned int seg[256];
    __shared__ unsigned int pref[256];
    int row = blockIdx.x;
    int t   = threadIdx.x;
    for (int i = t; i < 4096; i += 256) bins[i] = g_hist[row * 4096 + i];
    __syncthreads();
    unsigned int s = 0;
    for (int si = 0; si < 16; si++) s += bins[4095 - (t * 16 + si)];
    seg[t] = s;
    __syncthreads();
    if (t == 0) {
        unsigned int run = 0;
        for (int i = 0; i < 256; i++) { pref[i] = run; run += seg[i]; }
    }
    __syncthreads();
    int mk = *pmk;
    unsigned int need = (unsigned int)(mk < 1 ? 1 : (mk > CAP ? CAP : mk));
    if (pref[t] < need && pref[t] + seg[t] >= need) {
        unsigned int cum = pref[t];
        for (int si = 0; si < 16; si++) {
            int bin = 4095 - (t * 16 + si);
            cum += bins[bin];
            if (cum >= need) { g_thresh[row] = (unsigned int)bin; break; }
        }
    }
}

// ---------------- K6: collect candidates >= threshold bin ----------------
__global__ void k_collect(int N) {
    int row  = blockIdx.y;
    int base = blockIdx.x * 8192;
    unsigned int tb = g_thresh[row];
    const float* sr = g_scores + (size_t)row * N;
    for (int i = threadIdx.x; i < 8192; i += 256) {
        int idx = base + i;
        if (idx < N) {
            unsigned int u = fmono(sr[idx]);
            if ((u >> 20) >= tb) {
                int pos = atomicAdd(&g_ccount[row], 1);
                if (pos < CAP) {
                    g_cu  [row * CAP + pos] = u;
                    g_cidx[row * CAP + pos] = idx;
                }
            }
        }
    }
}

// ---------------- K7: exact rank within candidates, softmax(k_dyn), gather+agg ----------------
__global__ void k_final(const float* __restrict__ pool_params, const int* __restrict__ pkd,
                        float* __restrict__ out, int N) {
    __shared__ unsigned int cu[CAP];
    __shared__ int          ci[CAP];
    __shared__ float        selS[64];
    __shared__ int          selI[64];
    __shared__ float        w[64];
    int row = blockIdx.x;
    int c   = g_ccount[row]; if (c > CAP) c = CAP;
    for (int i = threadIdx.x; i < c; i += 256) {
        cu[i] = g_cu  [row * CAP + i];
        ci[i] = g_cidx[row * CAP + i];
    }
    __syncthreads();
    // exact rank: (key desc, index asc) matches jax.lax.top_k ordering & tie-break
    for (int i = threadIdx.x; i < c; i += 256) {
        unsigned int ui = cu[i];
        int idi = ci[i];
        int r = 0;
        for (int j = 0; j < c; j++) {
            unsigned int uj = cu[j];
            r += (uj > ui) || (uj == ui && ci[j] < idi);
        }
        if (r < 64) { selS[r] = funmono(ui); selI[r] = idi; }
    }
    __syncthreads();
    int kd = *pkd; if (kd > 64) kd = 64; if (kd < 1) kd = 1;
    if (threadIdx.x == 0) {
        float mx = selS[0];
        float sum = 0.f;
        for (int r = 0; r < kd; r++) { float e = expf(selS[r] - mx); w[r] = e; sum += e; }
        float inv = 1.0f / sum;
        for (int r = 0; r < kd; r++) w[r] *= inv;
    }
    __syncthreads();
    for (int d = threadIdx.x; d < 512; d += 256) {
        float acc = 0.f;
        for (int r = 0; r < kd; r++)
            acc += w[r] * pool_params[(size_t)selI[r] * 512 + d];
        out[row * 512 + d] = acc;
    }
}

// ---------------- launch ----------------
extern "C" void kernel_launch(void* const* d_in, const int* in_sizes, int n_in,
                              void* d_out, int out_size) {
    const float* hidden      = (const float*)d_in[0];
    const float* pool_params = (const float*)d_in[1];
    const float* pool_keys   = (const float*)d_in[2];
    const float* W           = (const float*)d_in[3];
    const float* bias        = (const float*)d_in[4];
    const int*   pkd         = (const int*)d_in[5];
    const int*   pmk         = (const int*)d_in[6];

    int B = out_size / 512;          if (B > MAXB) B = MAXB;
    int T = in_sizes[0] / (B * 512);
    int N = in_sizes[2] / 512;       if (N > MAXN) N = MAXN;

    k_zero<<<64, 512>>>();
    k_mean<<<dim3(B, 4), 128>>>(hidden, T);
    k_query<<<B, 128>>>(W, bias);
    k_scores<<<(N + TN - 1) / TN, 256>>>(pool_keys, N);
    dim3 hg((N + 8191) / 8192, B);
    k_hist<<<hg, 256>>>(N);
    k_thresh<<<B, 256>>>(pmk);
    k_collect<<<hg, 256>>>(N);
    k_final<<<B, 256>>>(pool_params, pkd, (float*)d_out, N);
}

// round 4
// speedup vs baseline: 1.3153x; 1.3153x over previous
#include <cuda_runtime.h>
#include <cuda_bf16.h>
#include <cstdint>

// ---------------- scratch (static __device__, no allocation) ----------------
#define MAXB 32
#define MAXN 500000
#define CAP  4096

__device__ float        g_pool8 [MAXB * 8 * 512];
__device__ float        g_query [MAXB * 512];
__device__ float        g_scores[(size_t)MAXB * MAXN];   // 64 MB
__device__ unsigned int g_rowmax[MAXB];
__device__ unsigned int g_hist16[MAXB * 16];
__device__ unsigned int g_thresh[MAXB];
__device__ int          g_ccount[MAXB];
__device__ unsigned int g_cu    [MAXB * CAP];
__device__ int          g_cidx  [MAXB * CAP];

__device__ __forceinline__ unsigned int fmono(float f) {
    unsigned int u = __float_as_uint(f);
    return (u & 0x80000000u) ? ~u : (u | 0x80000000u);
}
__device__ __forceinline__ float funmono(unsigned int u) {
    unsigned int o = (u & 0x80000000u) ? (u ^ 0x80000000u) : ~u;
    return __uint_as_float(o);
}

// packed fp32x2 FMA (FFMA2) — only reachable via PTX on sm_103a
__device__ __forceinline__ float2 ffma2(float2 a, float2 b, float2 c) {
    unsigned long long au = *reinterpret_cast<unsigned long long*>(&a);
    unsigned long long bu = *reinterpret_cast<unsigned long long*>(&b);
    unsigned long long cu = *reinterpret_cast<unsigned long long*>(&c);
    unsigned long long du;
    asm("fma.rn.f32x2 %0, %1, %2, %3;" : "=l"(du) : "l"(au), "l"(bu), "l"(cu));
    return *reinterpret_cast<float2*>(&du);
}

#define INV_SQRT_D 0.04419417382415922f   // 1/sqrt(512)

// ---------------- K0: zero small scratch ----------------
__global__ void k_zero() {
    int i = threadIdx.x;
    if (i < MAXB * 16) g_hist16[i] = 0u;
    if (i < MAXB) { g_ccount[i] = 0; g_rowmax[i] = 0u; }
}

// ---------------- K1: partial mean over T chunks ----------------
__global__ void k_mean(const float* __restrict__ hidden, int T) {
    int b  = blockIdx.x;
    int tc = blockIdx.y;              // 8 chunks
    int d  = threadIdx.x;             // 512 threads
    int rows_per = (T + 7) / 8;
    int t0 = tc * rows_per;
    int t1 = t0 + rows_per; if (t1 > T) t1 = T;
    const float* hp = hidden + ((size_t)b * T + t0) * 512 + d;
    float s0 = 0.f, s1 = 0.f, s2 = 0.f, s3 = 0.f;
    int nt = t1 - t0, t = 0;
    for (; t + 4 <= nt; t += 4) {
        s0 += hp[(size_t)(t + 0) * 512]; s1 += hp[(size_t)(t + 1) * 512];
        s2 += hp[(size_t)(t + 2) * 512]; s3 += hp[(size_t)(t + 3) * 512];
    }
    float s = (s0 + s1) + (s2 + s3);
    for (; t < nt; t++) s += hp[(size_t)t * 512];
    g_pool8[((size_t)b * 8 + tc) * 512 + d] = s;
}

// ---------------- K2: query = mean @ W + b ----------------
__global__ void k_query(const float* __restrict__ W, const float* __restrict__ bias, int T) {
    __shared__ float p[512];
    int b = blockIdx.x, tid = threadIdx.x;          // 128 threads
    float invT = 1.0f / (float)T;
    for (int i = tid; i < 512; i += 128) {
        float s = 0.f;
#pragma unroll
        for (int tc = 0; tc < 8; tc++) s += g_pool8[((size_t)b * 8 + tc) * 512 + i];
        p[i] = s * invT;
    }
    __syncthreads();
    int d = tid * 4;
    float a0 = 0.f, a1 = 0.f, a2 = 0.f, a3 = 0.f;
#pragma unroll 4
    for (int k = 0; k < 512; k++) {
        float4 wv = *reinterpret_cast<const float4*>(W + (size_t)k * 512 + d);
        float pv = p[k];
        a0 += pv * wv.x; a1 += pv * wv.y; a2 += pv * wv.z; a3 += pv * wv.w;
    }
    float4 bv = *reinterpret_cast<const float4*>(bias + d);
    float4 r  = make_float4(a0 + bv.x, a1 + bv.y, a2 + bv.z, a3 + bv.w);
    *reinterpret_cast<float4*>(g_query + (size_t)b * 512 + d) = r;
}

// ---------------- K3: scores GEMM, FMA-balanced ----------------
// Tile: 256 keys x 32 queries, K-chunk 32 (as 8 x float4 along K).
// 256 threads = 8 warps: warp -> (kg2 = w&1 key half, qg = w>>1 query quarter).
// Thread: 4 keys x 8 queries, K vectorized via FFMA2 pairs.
#define TN 256
__global__ __launch_bounds__(256, 2) void k_scores(const float* __restrict__ keys, int N) {
    __shared__ float4 ks4[8][TN + 1];   // [kp4][row]  ~32.9 KB
    __shared__ float4 qs4[8][33];       // [kp4][q]    ~4.2 KB
    int n0   = blockIdx.x * TN;
    int tid  = threadIdx.x;
    int lane = tid & 31;
    int w    = tid >> 5;
    int kg2  = w & 1;          // key half: 0/1 -> rows [0,128) / [128,256)
    int qg   = w >> 1;         // query quarter: 0..3 -> queries qg*8..+7
    int krow = lane + 128 * kg2;

    float2 acc[4][8];
#pragma unroll
    for (int i = 0; i < 4; i++)
#pragma unroll
        for (int j = 0; j < 8; j++) acc[i][j] = make_float2(0.f, 0.f);

    for (int c = 0; c < 512; c += 32) {
        // keys chunk: 256 rows x 8 float4 = 2048 / 256 thr = 8 each, coalesced
#pragma unroll
        for (int it = 0; it < 8; it++) {
            int v   = it * 256 + tid;
            int row = v >> 3;
            int c4  = v & 7;
            float4 val = make_float4(0.f, 0.f, 0.f, 0.f);
            int n = n0 + row;
            if (n < N)
                val = *reinterpret_cast<const float4*>(keys + (size_t)n * 512 + c + c4 * 4);
            ks4[c4][row] = val;
        }
        // query chunk: 32 q x 8 float4 = 256 -> 1 each
        {
            int q  = tid >> 3;
            int c4 = tid & 7;
            qs4[c4][q] = *reinterpret_cast<const float4*>(g_query + (size_t)q * 512 + c + c4 * 4);
        }
        __syncthreads();
#pragma unroll
        for (int kp = 0; kp < 8; kp++) {
            float4 kv[4];
#pragma unroll
            for (int i = 0; i < 4; i++) kv[i] = ks4[kp][krow + 32 * i];
#pragma unroll
            for (int jh = 0; jh < 2; jh++) {
                float4 qv[4];
#pragma unroll
                for (int j = 0; j < 4; j++) qv[j] = qs4[kp][qg * 8 + jh * 4 + j];
#pragma unroll
                for (int i = 0; i < 4; i++)
#pragma unroll
                    for (int j = 0; j < 4; j++) {
                        float2* a = &acc[i][jh * 4 + j];
                        *a = ffma2(make_float2(kv[i].x, kv[i].y),
                                   make_float2(qv[j].x, qv[j].y), *a);
                        *a = ffma2(make_float2(kv[i].z, kv[i].w),
                                   make_float2(qv[j].z, qv[j].w), *a);
                    }
            }
        }
        __syncthreads();
    }
    // epilogue: store scores + per-row running max (mono)
#pragma unroll
    for (int j = 0; j < 8; j++) {
        int m = qg * 8 + j;
        unsigned int um = 0u;
#pragma unroll
        for (int i = 0; i < 4; i++) {
            int n = n0 + krow + 32 * i;
            if (n < N) {
                float s = (acc[i][j].x + acc[i][j].y) * INV_SQRT_D;
                g_scores[(size_t)m * N + n] = s;
                unsigned int u = fmono(s);
                if (u > um) um = u;
            }
        }
        unsigned int wm = __reduce_max_sync(0xffffffffu, um);
        if (lane == 0) atomicMax(&g_rowmax[m], wm);
    }
}

// ---------------- K4: 16-bin hist restricted to top 2 octaves of rowmax ----------------
#define F4PB 8192   // float4s per block
__global__ void k_hist(int N) {
    __shared__ unsigned int h[16];
    int row = blockIdx.y;
    int N4  = N >> 2;
    if (threadIdx.x < 16) h[threadIdx.x] = 0u;
    __syncthreads();
    int lo = (int)(g_rowmax[row] >> 20) - 15;
    const float4* sr = reinterpret_cast<const float4*>(g_scores + (size_t)row * N);
    int base = blockIdx.x * F4PB;
    for (int i = threadIdx.x; i < F4PB; i += 256) {
        int i4 = base + i;
        if (i4 < N4) {
            float4 v = sr[i4];
            int b0 = (int)(fmono(v.x) >> 20) - lo;
            int b1 = (int)(fmono(v.y) >> 20) - lo;
            int b2 = (int)(fmono(v.z) >> 20) - lo;
            int b3 = (int)(fmono(v.w) >> 20) - lo;
            if (b0 >= 0) atomicAdd(&h[b0], 1u);
            if (b1 >= 0) atomicAdd(&h[b1], 1u);
            if (b2 >= 0) atomicAdd(&h[b2], 1u);
            if (b3 >= 0) atomicAdd(&h[b3], 1u);
        }
    }
    // scalar tail (N % 4), handled by block 0 only
    if (blockIdx.x == 0) {
        for (int idx = N4 * 4 + (int)threadIdx.x; idx < N; idx += 256) {
            int b = (int)(fmono(g_scores[(size_t)row * N + idx]) >> 20) - lo;
            if (b >= 0) atomicAdd(&h[b], 1u);
        }
    }
    __syncthreads();
    if (threadIdx.x < 16 && h[threadIdx.x])
        atomicAdd(&g_hist16[row * 16 + threadIdx.x], h[threadIdx.x]);
}

// ---------------- K5: pick threshold bin (cum from top >= max_k) ----------------
__global__ void k_thresh(const int* __restrict__ pmk) {
    int row = blockIdx.x;
    if (threadIdx.x == 0) {
        int lo = (int)(g_rowmax[row] >> 20) - 15;
        int mk = *pmk; if (mk < 1) mk = 1; if (mk > CAP) mk = CAP;
        unsigned int cum = 0;
        int tb = lo;   // fallback: everything in range
        for (int b = 15; b >= 0; b--) {
            cum += g_hist16[row * 16 + b];
            if (cum >= (unsigned int)mk) { tb = lo + b; break; }
        }
        g_thresh[row] = (unsigned int)tb;
    }
}

// ---------------- K6: collect candidates with bin >= threshold ----------------
__global__ void k_collect(int N) {
    int row = blockIdx.y;
    int N4  = N >> 2;
    unsigned int tb = g_thresh[row];
    const float4* sr = reinterpret_cast<const float4*>(g_scores + (size_t)row * N);
    int base = blockIdx.x * F4PB;
    for (int i = threadIdx.x; i < F4PB; i += 256) {
        int i4 = base + i;
        if (i4 < N4) {
            float4 v = sr[i4];
            unsigned int u[4] = {fmono(v.x), fmono(v.y), fmono(v.z), fmono(v.w)};
#pragma unroll
            for (int e = 0; e < 4; e++) {
                if ((u[e] >> 20) >= tb) {
                    int pos = atomicAdd(&g_ccount[row], 1);
                    if (pos < CAP) {
                        g_cu  [row * CAP + pos] = u[e];
                        g_cidx[row * CAP + pos] = i4 * 4 + e;
                    }
                }
            }
        }
    }
    if (blockIdx.x == 0) {
        for (int idx = N4 * 4 + (int)threadIdx.x; idx < N; idx += 256) {
            unsigned int u = fmono(g_scores[(size_t)row * N + idx]);
            if ((u >> 20) >= tb) {
                int pos = atomicAdd(&g_ccount[row], 1);
                if (pos < CAP) {
                    g_cu  [row * CAP + pos] = u;
                    g_cidx[row * CAP + pos] = idx;
                }
            }
        }
    }
}

// ---------------- K7: exact rank, softmax(k_dyn), gather + aggregate ----------------
__global__ void k_final(const float* __restrict__ pool_params, const int* __restrict__ pkd,
                        float* __restrict__ out, int N) {
    __shared__ unsigned int cu[CAP];
    __shared__ int          ci[CAP];
    __shared__ float        selS[64];
    __shared__ int          selI[64];
    __shared__ float        w[64];
    int row = blockIdx.x;
    int c   = g_ccount[row]; if (c > CAP) c = CAP;
    for (int i = threadIdx.x; i < c; i += 256) {
        cu[i] = g_cu  [row * CAP + i];
        ci[i] = g_cidx[row * CAP + i];
    }
    __syncthreads();
    // exact rank: (key desc, index asc) matches jax.lax.top_k ordering & tie-break
    for (int i = threadIdx.x; i < c; i += 256) {
        unsigned int ui = cu[i];
        int idi = ci[i];
        int r = 0;
        for (int j = 0; j < c; j++) {
            unsigned int uj = cu[j];
            r += (uj > ui) || (uj == ui && ci[j] < idi);
        }
        if (r < 64) { selS[r] = funmono(ui); selI[r] = idi; }
    }
    __syncthreads();
    int kd = *pkd; if (kd > 64) kd = 64; if (kd < 1) kd = 1;
    if (kd > c) kd = c;
    if (threadIdx.x == 0) {
        float mx = selS[0];
        float sum = 0.f;
        for (int r = 0; r < kd; r++) { float e = expf(selS[r] - mx); w[r] = e; sum += e; }
        float inv = 1.0f / sum;
        for (int r = 0; r < kd; r++) w[r] *= inv;
    }
    __syncthreads();
    for (int d = threadIdx.x; d < 512; d += 256) {
        float acc = 0.f;
        for (int r = 0; r < kd; r++)
            acc += w[r] * pool_params[(size_t)selI[r] * 512 + d];
        out[row * 512 + d] = acc;
    }
}

// ---------------- launch ----------------
extern "C" void kernel_launch(void* const* d_in, const int* in_sizes, int n_in,
                              void* d_out, int out_size) {
    const float* hidden      = (const float*)d_in[0];
    const float* pool_params = (const float*)d_in[1];
    const float* pool_keys   = (const float*)d_in[2];
    const float* W           = (const float*)d_in[3];
    const float* bias        = (const float*)d_in[4];
    const int*   pkd         = (const int*)d_in[5];
    const int*   pmk         = (const int*)d_in[6];

    int B = out_size / 512;          if (B > MAXB) B = MAXB;
    int T = in_sizes[0] / (B * 512);
    int N = in_sizes[2] / 512;       if (N > MAXN) N = MAXN;

    k_zero<<<1, 1024>>>();
    k_mean<<<dim3(B, 8), 512>>>(hidden, T);
    k_query<<<B, 128>>>(W, bias, T);
    k_scores<<<(N + TN - 1) / TN, 256>>>(pool_keys, N);
    int gx = ((N >> 2) + F4PB - 1) / F4PB;
    k_hist<<<dim3(gx, B), 256>>>(N);
    k_thresh<<<B, 32>>>(pmk);
    k_collect<<<dim3(gx, B), 256>>>(N);
    k_final<<<B, 256>>>(pool_params, pkd, (float*)d_out, N);
}